// round 2
// baseline (speedup 1.0000x reference)
#include <cuda_runtime.h>
#include <cuda_bf16.h>

#define TQ      32      // queries per block
#define THREADS 256
#define WIN     9
#define EDGE    4

__global__ __launch_bounds__(THREADS)
void hwnet_kernel(const float* __restrict__ x,
                  const float* __restrict__ etab,
                  const float* __restrict__ tctab,
                  const float* __restrict__ vtab,
                  float* __restrict__ out,
                  int B, int T)
{
    __shared__ float s_score[TQ][WIN];
    __shared__ int   s_base[TQ];

    const int tid    = threadIdx.x;
    const int qblock = blockIdx.x * TQ;

    // ---- Phase 1: one warp computes nearest-idx + softmax weights (9 MUFU/query, no redundancy)
    if (tid < TQ) {
        const int q = qblock + tid;
        float xv = (q < B) ? x[q] : 0.0f;

        // binary search: count of table entries <= xv  (table sorted ascending)
        int lo = 0, hi = T;
        while (lo < hi) {
            int mid = (lo + hi) >> 1;
            if (__ldg(&etab[mid]) <= xv) lo = mid + 1; else hi = mid;
        }
        int c1 = max(lo - 1, 0);
        int c2 = min(lo, T - 1);
        // exact fp32 squared distances, argmin first-occurrence tie-break (<=) -> lower index
        float d1 = xv - __ldg(&etab[c1]); d1 *= d1;
        float d2 = xv - __ldg(&etab[c2]); d2 *= d2;
        int idx = (d1 <= d2) ? c1 : c2;

        float tc = __ldg(&tctab[idx]);              // UNCLIPPED idx (matches reference)
        int idx_c = min(max(idx, EDGE), T - 1 - EDGE);
        int base = idx_c - EDGE;

        float logit[WIN];
        float m = -1e30f;
        #pragma unroll
        for (int j = 0; j < WIN; j++) {
            float e = __ldg(&etab[base + j]);
            float d = xv - e;
            float l = -(d * d) * tc;
            logit[j] = l;
            m = fmaxf(m, l);
        }
        float sum = 0.0f;
        #pragma unroll
        for (int j = 0; j < WIN; j++) {
            float p = __expf(logit[j] - m);
            logit[j] = p;
            sum += p;
        }
        float inv = __frcp_rn(sum);
        #pragma unroll
        for (int j = 0; j < WIN; j++) s_score[tid][j] = logit[j] * inv;
        s_base[tid] = base;
    }
    __syncthreads();

    // ---- Phase 2: 8 threads per query, each owns 8 contiguous floats of D=64
    const int q    = tid >> 3;      // 0..31
    const int lane = tid & 7;       // 0..7
    const int gq   = qblock + q;
    if (gq >= B) return;

    const int base = s_base[q];
    float4 a0 = make_float4(0.f, 0.f, 0.f, 0.f);
    float4 a1 = make_float4(0.f, 0.f, 0.f, 0.f);
    const float4* vt = (const float4*)vtab;     // rows of 16 float4

    #pragma unroll
    for (int j = 0; j < WIN; j++) {
        float w = s_score[q][j];
        const float4* row = vt + (size_t)(base + j) * 16 + lane * 2;
        float4 v0 = __ldg(row);
        float4 v1 = __ldg(row + 1);
        a0.x = fmaf(w, v0.x, a0.x);
        a0.y = fmaf(w, v0.y, a0.y);
        a0.z = fmaf(w, v0.z, a0.z);
        a0.w = fmaf(w, v0.w, a0.w);
        a1.x = fmaf(w, v1.x, a1.x);
        a1.y = fmaf(w, v1.y, a1.y);
        a1.z = fmaf(w, v1.z, a1.z);
        a1.w = fmaf(w, v1.w, a1.w);
    }

    float4* o = (float4*)(out + (size_t)gq * 64) + lane * 2;
    o[0] = a0;
    o[1] = a1;
}

extern "C" void kernel_launch(void* const* d_in, const int* in_sizes, int n_in,
                              void* d_out, int out_size)
{
    const float* x    = (const float*)d_in[0];   // [B,1]
    const float* etab = (const float*)d_in[1];   // [T,1]
    const float* tctab= (const float*)d_in[2];   // [T,1]
    const float* vtab = (const float*)d_in[3];   // [T,D]
    // d_in[4] = idx_table [-E..E], window hardcoded via EDGE/WIN
    float* out = (float*)d_out;

    const int B = in_sizes[0];                   // 131072
    const int T = in_sizes[1];                   // 2048

    const int blocks = (B + TQ - 1) / TQ;
    hwnet_kernel<<<blocks, THREADS>>>(x, etab, tctab, vtab, out, B, T);
}

// round 4
// speedup vs baseline: 1.4917x; 1.4917x over previous
#include <cuda_runtime.h>
#include <cuda_bf16.h>

#define THREADS 256
#define WIN     9
#define EDGE    4
#define QPW     4      // queries per warp (8 lanes each)

__global__ __launch_bounds__(THREADS)
void hwnet_kernel(const float* __restrict__ x,
                  const float* __restrict__ etab,
                  const float* __restrict__ tctab,
                  const float* __restrict__ vtab,
                  float* __restrict__ out,
                  int B, int T)
{
    const int tid  = threadIdx.x;
    const int warp = tid >> 5;
    const int lane = tid & 31;
    const int qwarp = (blockIdx.x * (THREADS / 32) + warp) * QPW; // first query of this warp

    // ---- Phase 1 (lanes 0..3): analytic nearest-index + exact argmin verify + softmax
    float score[WIN];
    int base = 0;
    if (lane < QPW) {
        const int q = qwarp + lane;
        const float xv = x[min(q, B - 1)];

        const float e0 = __ldg(&etab[0]);
        const float eN = __ldg(&etab[T - 1]);
        const float step = (eN - e0) / (float)(T - 1);
        int i0 = (int)floorf((xv - e0) / step);

        // exact argmin over candidates i0-1..i0+2 (covers any fp rounding in i0);
        // ascending scan with strict '<' == jnp.argmin first-occurrence tie-break
        int idx = 0;
        float best = 3.4e38f;
        #pragma unroll
        for (int k = 0; k < 4; k++) {
            int cc = min(max(i0 - 1 + k, 0), T - 1);
            float d = xv - __ldg(&etab[cc]);
            d *= d;
            if (d < best) { best = d; idx = cc; }
        }

        const float tc = __ldg(&tctab[idx]);            // UNCLIPPED idx (matches reference)
        const int idx_c = min(max(idx, EDGE), T - 1 - EDGE);
        base = idx_c - EDGE;

        float logit[WIN];
        float m = -3.4e38f;
        #pragma unroll
        for (int j = 0; j < WIN; j++) {
            float e = __ldg(&etab[base + j]);
            float d = xv - e;
            float l = -(d * d) * tc;
            logit[j] = l;
            m = fmaxf(m, l);
        }
        float sum = 0.0f;
        #pragma unroll
        for (int j = 0; j < WIN; j++) {
            float p = __expf(logit[j] - m);
            logit[j] = p;
            sum += p;
        }
        const float inv = __frcp_rn(sum);
        #pragma unroll
        for (int j = 0; j < WIN; j++) score[j] = logit[j] * inv;
    }

    // ---- Broadcast weights/base to the 8 lanes owning each query (no block barrier)
    const int q   = lane >> 3;      // 0..3: which of the warp's queries this lane serves
    const int sub = lane & 7;       // 0..7: which 16B chunk of D=64
    const int b   = __shfl_sync(0xffffffffu, base, q);
    float w[WIN];
    #pragma unroll
    for (int j = 0; j < WIN; j++) w[j] = __shfl_sync(0xffffffffu, score[j], q);

    const int gq = qwarp + q;
    if (gq >= B) return;

    // ---- Phase 2: coalesced gather — lane sub owns chunks [sub] and [sub+8] of each 256B row
    const float4* vt = (const float4*)vtab;     // rows of 16 float4
    float4 a0 = make_float4(0.f, 0.f, 0.f, 0.f);
    float4 a1 = make_float4(0.f, 0.f, 0.f, 0.f);

    #pragma unroll
    for (int j = 0; j < WIN; j++) {
        const float4* row = vt + (size_t)(b + j) * 16;
        float4 v0 = __ldg(row + sub);
        float4 v1 = __ldg(row + 8 + sub);
        float wj = w[j];
        a0.x = fmaf(wj, v0.x, a0.x);
        a0.y = fmaf(wj, v0.y, a0.y);
        a0.z = fmaf(wj, v0.z, a0.z);
        a0.w = fmaf(wj, v0.w, a0.w);
        a1.x = fmaf(wj, v1.x, a1.x);
        a1.y = fmaf(wj, v1.y, a1.y);
        a1.z = fmaf(wj, v1.z, a1.z);
        a1.w = fmaf(wj, v1.w, a1.w);
    }

    float4* o = (float4*)(out + (size_t)gq * 64);
    o[sub]     = a0;
    o[8 + sub] = a1;
}

extern "C" void kernel_launch(void* const* d_in, const int* in_sizes, int n_in,
                              void* d_out, int out_size)
{
    const float* x     = (const float*)d_in[0];   // [B,1]
    const float* etab  = (const float*)d_in[1];   // [T,1]
    const float* tctab = (const float*)d_in[2];   // [T,1]
    const float* vtab  = (const float*)d_in[3];   // [T,D]
    float* out = (float*)d_out;

    const int B = in_sizes[0];                    // 131072
    const int T = in_sizes[1];                    // 2048

    const int qpb    = (THREADS / 32) * QPW;      // 32 queries per block
    const int blocks = (B + qpb - 1) / qpb;
    hwnet_kernel<<<blocks, THREADS>>>(x, etab, tctab, vtab, out, B, T);
}